// round 1
// baseline (speedup 1.0000x reference)
#include <cuda_runtime.h>

#define THREADS 512
#define KHALF   512
#define KTOTAL  1024
#define D       64
#define HW      4096   // 64*64 spatial

// Packed dual-fp32 FMA (Blackwell f32x2 pipe; ptxas never auto-fuses this).
__device__ __forceinline__ void fma2(unsigned long long &acc,
                                     unsigned long long a,
                                     unsigned long long b) {
    asm("fma.rn.f32x2 %0, %1, %2, %0;" : "+l"(acc) : "l"(a), "l"(b));
}

__global__ void __launch_bounds__(THREADS, 1)
vq_kernel(const float* __restrict__ input,
          const float* __restrict__ codebook,
          float* __restrict__ out) {
    extern __shared__ float smem[];
    float* cb  = smem;               // [KHALF * D]
    float* sse = smem + KHALF * D;   // [KHALF]

    const int t  = blockIdx.x * THREADS + threadIdx.x;   // token id, exact cover
    const int b  = t >> 12;                               // t / 4096
    const int hw = t & (HW - 1);
    const float* in = input + (size_t)b * D * HW + hw;

    // Load this token's 64 features (stride-4096, warp-coalesced per d),
    // pack into 32 f32x2 registers, accumulate ||x||^2.
    unsigned long long xp[D / 2];
    float ssx = 0.0f;
#pragma unroll
    for (int j = 0; j < D / 2; ++j) {
        float lo = in[(2 * j) * HW];
        float hi = in[(2 * j + 1) * HW];
        ssx += lo * lo;
        ssx += hi * hi;
        asm("mov.b64 %0, {%1, %2};" : "=l"(xp[j]) : "f"(lo), "f"(hi));
    }

    float best = 3.4e38f;
    int   bidx = 0;

    for (int half = 0; half < 2; ++half) {
        __syncthreads();  // protect smem reuse across halves
        // Stage 512 codes (128 KB) into smem, coalesced float4.
        const float4* src = (const float4*)(codebook + half * KHALF * D);
        float4*       dst = (float4*)cb;
#pragma unroll
        for (int i = 0; i < (KHALF * D / 4) / THREADS; ++i)
            dst[threadIdx.x + i * THREADS] = src[threadIdx.x + i * THREADS];
        __syncthreads();

        // Per-code ||e||^2 (thread k sums its row — trivial cost).
        {
            const float* row = cb + threadIdx.x * D;
            float s = 0.0f;
#pragma unroll
            for (int d0 = 0; d0 < D; ++d0) s += row[d0] * row[d0];
            sse[threadIdx.x] = s;
        }
        __syncthreads();

        for (int k = 0; k < KHALF; ++k) {
            const ulonglong2* row = (const ulonglong2*)(cb + k * D);
            unsigned long long a0 = 0, a1 = 0, a2 = 0, a3 = 0;
#pragma unroll
            for (int j = 0; j < 16; j += 4) {
                ulonglong2 v0 = row[j];
                ulonglong2 v1 = row[j + 1];
                ulonglong2 v2 = row[j + 2];
                ulonglong2 v3 = row[j + 3];
                fma2(a0, xp[2 * j    ], v0.x);
                fma2(a1, xp[2 * j + 1], v0.y);
                fma2(a2, xp[2 * j + 2], v1.x);
                fma2(a3, xp[2 * j + 3], v1.y);
                fma2(a0, xp[2 * j + 4], v2.x);
                fma2(a1, xp[2 * j + 5], v2.y);
                fma2(a2, xp[2 * j + 6], v3.x);
                fma2(a3, xp[2 * j + 7], v3.y);
            }
            float l0, h0, l1, h1, l2, h2, l3, h3;
            asm("mov.b64 {%0,%1}, %2;" : "=f"(l0), "=f"(h0) : "l"(a0));
            asm("mov.b64 {%0,%1}, %2;" : "=f"(l1), "=f"(h1) : "l"(a1));
            asm("mov.b64 {%0,%1}, %2;" : "=f"(l2), "=f"(h2) : "l"(a2));
            asm("mov.b64 {%0,%1}, %2;" : "=f"(l3), "=f"(h3) : "l"(a3));
            float dot  = ((l0 + h0) + (l1 + h1)) + ((l2 + h2) + (l3 + h3));
            // Reference formula shape: (||x||^2 + ||e||^2) - 2*x.e  (2*dot exact)
            float dist = (ssx + sse[k]) - 2.0f * dot;
            if (dist < best) { best = dist; bidx = half * KHALF + k; }
        }
    }

    // Gather chosen code row from L2 and scatter to NCHW output.
    const float4* e  = (const float4*)codebook + bidx * (D / 4);
    float*        op = out + (size_t)b * D * HW + hw;
#pragma unroll
    for (int j = 0; j < D / 4; ++j) {
        float4 v = __ldg(e + j);
        op[(4 * j + 0) * HW] = v.x;
        op[(4 * j + 1) * HW] = v.y;
        op[(4 * j + 2) * HW] = v.z;
        op[(4 * j + 3) * HW] = v.w;
    }
}

extern "C" void kernel_launch(void* const* d_in, const int* in_sizes, int n_in,
                              void* d_out, int out_size) {
    const float* input    = (const float*)d_in[0];   // [16, 64, 64, 64] fp32
    const float* codebook = (const float*)d_in[1];   // [1024, 64] fp32
    float*       out      = (float*)d_out;           // [16, 64, 64, 64] fp32

    size_t smem_bytes = (size_t)(KHALF * D + KHALF) * sizeof(float);  // 133120 B
    cudaFuncSetAttribute(vq_kernel, cudaFuncAttributeMaxDynamicSharedMemorySize,
                         (int)smem_bytes);
    vq_kernel<<<(KTOTAL * D == 0 ? 0 : 128), THREADS, smem_bytes>>>(input, codebook, out);
}

// round 3
// speedup vs baseline: 1.2158x; 1.2158x over previous
#include <cuda_runtime.h>

#define THREADS 256
#define TPT     2      // tokens per thread
#define KHALF   512
#define KTOTAL  1024
#define D       64
#define HW      4096   // 64*64 spatial

// Packed dual-fp32 FMA / ADD (Blackwell f32x2 pipe; ptxas never auto-fuses).
__device__ __forceinline__ void fma2(unsigned long long &acc,
                                     unsigned long long a,
                                     unsigned long long b) {
    asm("fma.rn.f32x2 %0, %1, %2, %0;" : "+l"(acc) : "l"(a), "l"(b));
}
__device__ __forceinline__ unsigned long long add2(unsigned long long a,
                                                   unsigned long long b) {
    unsigned long long r;
    asm("add.rn.f32x2 %0, %1, %2;" : "=l"(r) : "l"(a), "l"(b));
    return r;
}

__global__ void __launch_bounds__(THREADS, 1)
vq_kernel(const float* __restrict__ input,
          const float* __restrict__ codebook,
          float* __restrict__ out) {
    extern __shared__ float smem[];
    float* cb  = smem;               // [KHALF * D]
    float* sse = smem + KHALF * D;   // [KHALF]

    const int tid = threadIdx.x;
    const int t0  = blockIdx.x * (THREADS * TPT) + tid;

    // Two tokens per thread, features packed as f32x2 pairs across dims.
    unsigned long long xp[TPT][D / 2];   // 32 pairs per token = full 64 dims
    float ssx[TPT];

    #pragma unroll
    for (int u = 0; u < TPT; ++u) {
        const int t  = t0 + u * THREADS;       // warp-coalesced
        const int b  = t >> 12;
        const int hw = t & (HW - 1);
        const float* in = input + (size_t)b * D * HW + hw;
        float s = 0.0f;
        #pragma unroll
        for (int j = 0; j < D / 2; ++j) {
            float lo = in[(2 * j) * HW];
            float hi = in[(2 * j + 1) * HW];
            s += lo * lo;
            s += hi * hi;
            asm("mov.b64 %0, {%1, %2};" : "=l"(xp[u][j]) : "f"(lo), "f"(hi));
        }
        ssx[u] = s;
    }

    float best[TPT];
    int   bidx[TPT];
    #pragma unroll
    for (int u = 0; u < TPT; ++u) { best[u] = 3.4e38f; bidx[u] = 0; }

    for (int half = 0; half < 2; ++half) {
        __syncthreads();  // protect smem reuse across halves
        // Stage 512 codes (128 KB) into smem, coalesced float4.
        const float4* src = (const float4*)(codebook + half * KHALF * D);
        float4*       dst = (float4*)cb;
        #pragma unroll
        for (int i = 0; i < (KHALF * D / 4) / THREADS; ++i)
            dst[tid + i * THREADS] = src[tid + i * THREADS];
        __syncthreads();

        // Per-code ||e||^2 (2 rows per thread).
        #pragma unroll
        for (int r = 0; r < KHALF / THREADS; ++r) {
            const int k = tid + r * THREADS;
            const float* row = cb + k * D;
            float s = 0.0f;
            #pragma unroll
            for (int d0 = 0; d0 < D; ++d0) s += row[d0] * row[d0];
            sse[k] = s;
        }
        __syncthreads();

        for (int k = 0; k < KHALF; ++k) {
            const ulonglong2* row = (const ulonglong2*)(cb + k * D);
            const float c = sse[k];

            // Persistent accumulators for both tokens across the two row chunks.
            unsigned long long acc[TPT][4];
            #pragma unroll
            for (int u = 0; u < TPT; ++u)
                #pragma unroll
                for (int a = 0; a < 4; ++a) acc[u][a] = 0ULL;

            // Row read in two chunks of 8 LDS.128 (32 floats each);
            // each chunk reused by both tokens.
            #pragma unroll
            for (int cchunk = 0; cchunk < 2; ++cchunk) {
                ulonglong2 r[8];
                #pragma unroll
                for (int j = 0; j < 8; ++j) r[j] = row[cchunk * 8 + j];

                #pragma unroll
                for (int u = 0; u < TPT; ++u) {
                    #pragma unroll
                    for (int j = 0; j < 8; j += 2) {
                        const int xb = cchunk * 16 + 2 * j;  // ulonglong index base
                        fma2(acc[u][0], xp[u][xb + 0], r[j].x);
                        fma2(acc[u][1], xp[u][xb + 1], r[j].y);
                        fma2(acc[u][2], xp[u][xb + 2], r[j + 1].x);
                        fma2(acc[u][3], xp[u][xb + 3], r[j + 1].y);
                    }
                }
            }

            #pragma unroll
            for (int u = 0; u < TPT; ++u) {
                unsigned long long s01 = add2(acc[u][0], acc[u][1]);
                unsigned long long s23 = add2(acc[u][2], acc[u][3]);
                unsigned long long s   = add2(s01, s23);
                float lo, hi;
                asm("mov.b64 {%0, %1}, %2;" : "=f"(lo), "=f"(hi) : "l"(s));
                const float dot  = lo + hi;
                const float dist = (ssx[u] + c) - 2.0f * dot;
                if (dist < best[u]) { best[u] = dist; bidx[u] = half * KHALF + k; }
            }
        }
    }

    // Gather chosen code rows from L2 and scatter to NCHW output.
    #pragma unroll
    for (int u = 0; u < TPT; ++u) {
        const int t  = t0 + u * THREADS;
        const int b  = t >> 12;
        const int hw = t & (HW - 1);
        const float4* e  = (const float4*)codebook + bidx[u] * (D / 4);
        float*        op = out + (size_t)b * D * HW + hw;
        #pragma unroll
        for (int j = 0; j < D / 4; ++j) {
            float4 v = __ldg(e + j);
            op[(4 * j + 0) * HW] = v.x;
            op[(4 * j + 1) * HW] = v.y;
            op[(4 * j + 2) * HW] = v.z;
            op[(4 * j + 3) * HW] = v.w;
        }
    }
}

extern "C" void kernel_launch(void* const* d_in, const int* in_sizes, int n_in,
                              void* d_out, int out_size) {
    const float* input    = (const float*)d_in[0];   // [16, 64, 64, 64] fp32
    const float* codebook = (const float*)d_in[1];   // [1024, 64] fp32
    float*       out      = (float*)d_out;           // [16, 64, 64, 64] fp32

    size_t smem_bytes = (size_t)(KHALF * D + KHALF) * sizeof(float);  // 133120 B
    cudaFuncSetAttribute(vq_kernel, cudaFuncAttributeMaxDynamicSharedMemorySize,
                         (int)smem_bytes);
    vq_kernel<<<128, THREADS, smem_bytes>>>(input, codebook, out);
}

// round 4
// speedup vs baseline: 1.9610x; 1.6130x over previous
#include <cuda_runtime.h>

#define D      64
#define KCODES 1024
#define NTOK   65536
#define HW     4096

// Scratch (device globals — no allocation allowed).
__device__ float g_Ehi[KCODES * D];   // codebook hi-plane, B-fragment order
__device__ float g_Elo[KCODES * D];   // codebook lo-plane, B-fragment order
__device__ float g_sse[KCODES];      // ||e_k||^2
__device__ float g_pd[4 * NTOK];     // per-quarter best dist
__device__ int   g_pi[4 * NTOK];     // per-quarter best idx

__device__ __forceinline__ float tf32_rna(float x) {
    unsigned u;
    asm("cvt.rna.tf32.f32 %0, %1;" : "=r"(u) : "f"(x));
    return __uint_as_float(u);
}

// D += A(tf32 16x8) * B(tf32 8x8), fp32 accumulate.
__device__ __forceinline__ void mma_tf32(float c[4], const float* a, float b0, float b1) {
    asm("mma.sync.aligned.m16n8k8.row.col.f32.tf32.tf32.f32 "
        "{%0,%1,%2,%3}, {%4,%5,%6,%7}, {%8,%9}, {%0,%1,%2,%3};"
        : "+f"(c[0]), "+f"(c[1]), "+f"(c[2]), "+f"(c[3])
        : "r"(__float_as_uint(a[0])), "r"(__float_as_uint(a[1])),
          "r"(__float_as_uint(a[2])), "r"(__float_as_uint(a[3])),
          "r"(__float_as_uint(b0)),   "r"(__float_as_uint(b1)));
}

// ---------------- prep: codebook -> hi/lo B-fragments + sse ----------------
// B-frag layout for m16n8k8 .col: b_j = B[k = lane%4 + 4j][n = lane/4]
//   = E[n][k].  Linear slot: ((ntile*8 + kstep)*32 + lane)*2 + j.
__global__ void vq_prep(const float* __restrict__ cb) {
    int tid = blockIdx.x * blockDim.x + threadIdx.x;   // 65536 = 1024*64
    int n = tid >> 6, k = tid & 63;
    float e  = cb[n * D + k];
    float hi = tf32_rna(e);
    float lo = e - hi;
    int ntile = n >> 3, kstep = k >> 3;
    int lane  = ((n & 7) << 2) + (k & 3);
    int j     = (k >> 2) & 1;
    int idx   = ((ntile * 8 + kstep) * 32 + lane) * 2 + j;
    g_Ehi[idx] = hi;
    g_Elo[idx] = lo;
    if (k == 0) {   // sse, sequential order (matches R3-passing kernel)
        const float* row = cb + n * D;
        float s = 0.0f;
        for (int d = 0; d < D; ++d) s += row[d] * row[d];
        g_sse[n] = s;
    }
}

// ---------------- main: 3xTF32 GEMM + argmin over a code quarter ----------
__global__ void __launch_bounds__(256, 1)
vq_main(const float* __restrict__ input) {
    extern __shared__ float sm[];
    float* sEhi = sm;             // 16384 floats (256 codes * 64 dims, frag order)
    float* sElo = sm + 16384;     // 16384
    float* sSse = sm + 32768;     // 256

    const int q   = blockIdx.y;          // code quarter
    const int tid = threadIdx.x;

    // Stage this quarter's fragments (contiguous 16384-float range per quarter).
    {
        const float4* srch = (const float4*)g_Ehi + q * 4096;
        const float4* srcl = (const float4*)g_Elo + q * 4096;
        float4* dh = (float4*)sEhi;
        float4* dl = (float4*)sElo;
        #pragma unroll
        for (int i = 0; i < 16; ++i) {
            dh[tid + i * 256] = srch[tid + i * 256];
            dl[tid + i * 256] = srcl[tid + i * 256];
        }
        sSse[tid] = g_sse[q * 256 + tid];
    }
    __syncthreads();

    const int w    = tid >> 5;
    const int lane = tid & 31;
    const int grp  = lane >> 2;   // row group 0..7
    const int cb4  = lane & 3;    // col group 0..3

    #pragma unroll 1
    for (int mt = 0; mt < 16; ++mt) {
        // A fragment: 16 tokens (rows), 64 dims, hi+lo planes.
        const int row0 = blockIdx.x * 2048 + (w * 16 + mt) * 16 + grp;  // + row1 = row0+8
        const int b    = row0 >> 12;
        const int hw   = row0 & (HW - 1);
        const float* p0 = input + (size_t)b * D * HW + hw;
        const float* p1 = p0 + 8;

        float Ahi[32], Alo[32];
        float ssx0 = 0.0f, ssx1 = 0.0f;
        #pragma unroll
        for (int ks = 0; ks < 8; ++ks) {
            const int d0 = ks * 8 + cb4;
            float x00 = p0[(size_t)d0 * HW];
            float x10 = p1[(size_t)d0 * HW];
            float x01 = p0[(size_t)(d0 + 4) * HW];
            float x11 = p1[(size_t)(d0 + 4) * HW];
            ssx0 = fmaf(x00, x00, ssx0);  ssx0 = fmaf(x01, x01, ssx0);
            ssx1 = fmaf(x10, x10, ssx1);  ssx1 = fmaf(x11, x11, ssx1);
            float h;
            h = tf32_rna(x00); Ahi[ks * 4 + 0] = h; Alo[ks * 4 + 0] = x00 - h;
            h = tf32_rna(x10); Ahi[ks * 4 + 1] = h; Alo[ks * 4 + 1] = x10 - h;
            h = tf32_rna(x01); Ahi[ks * 4 + 2] = h; Alo[ks * 4 + 2] = x01 - h;
            h = tf32_rna(x11); Ahi[ks * 4 + 3] = h; Alo[ks * 4 + 3] = x11 - h;
        }
        // ssx: common-mode per token — any fp32-accurate order is fine.
        ssx0 += __shfl_xor_sync(0xffffffffu, ssx0, 1);
        ssx0 += __shfl_xor_sync(0xffffffffu, ssx0, 2);
        ssx1 += __shfl_xor_sync(0xffffffffu, ssx1, 1);
        ssx1 += __shfl_xor_sync(0xffffffffu, ssx1, 2);

        float best0 = 3.4e38f, best1 = 3.4e38f;
        int   bi0 = 0, bi1 = 0;

        #pragma unroll 1
        for (int ng = 0; ng < 8; ++ng) {      // 4 n-tiles (32 codes) per group
            float C[4][4];
            #pragma unroll
            for (int u = 0; u < 4; ++u)
                #pragma unroll
                for (int v = 0; v < 4; ++v) C[u][v] = 0.0f;

            #pragma unroll
            for (int ks = 0; ks < 8; ++ks) {
                #pragma unroll
                for (int u = 0; u < 4; ++u) {
                    const int off = (((ng * 4 + u) * 8 + ks) * 32 + lane) * 2;
                    float2 bh = *(const float2*)&sEhi[off];
                    float2 bl = *(const float2*)&sElo[off];
                    mma_tf32(C[u], &Ahi[ks * 4], bh.x, bh.y);  // hi*hi
                    mma_tf32(C[u], &Ahi[ks * 4], bl.x, bl.y);  // hi*lo
                    mma_tf32(C[u], &Alo[ks * 4], bh.x, bh.y);  // lo*hi
                }
            }

            #pragma unroll
            for (int u = 0; u < 4; ++u) {
                const int ncol = (ng * 4 + u) * 8 + 2 * cb4;
                float2 ss = *(const float2*)&sSse[ncol];
                const int kg = q * 256 + ncol;
                // Same formula shape as the passing scalar kernels.
                float d00 = (ssx0 + ss.x) - 2.0f * C[u][0];
                float d01 = (ssx0 + ss.y) - 2.0f * C[u][1];
                float d10 = (ssx1 + ss.x) - 2.0f * C[u][2];
                float d11 = (ssx1 + ss.y) - 2.0f * C[u][3];
                if (d00 < best0) { best0 = d00; bi0 = kg;     }
                if (d01 < best0) { best0 = d01; bi0 = kg + 1; }
                if (d10 < best1) { best1 = d10; bi1 = kg;     }
                if (d11 < best1) { best1 = d11; bi1 = kg + 1; }
            }
        }

        // Reduce over the 4 lanes of each row group; ties -> lower index.
        #pragma unroll
        for (int o = 1; o <= 2; o <<= 1) {
            float od; int oi;
            od = __shfl_xor_sync(0xffffffffu, best0, o);
            oi = __shfl_xor_sync(0xffffffffu, bi0,   o);
            if (od < best0 || (od == best0 && oi < bi0)) { best0 = od; bi0 = oi; }
            od = __shfl_xor_sync(0xffffffffu, best1, o);
            oi = __shfl_xor_sync(0xffffffffu, bi1,   o);
            if (od < best1 || (od == best1 && oi < bi1)) { best1 = od; bi1 = oi; }
        }
        if (cb4 == 0) {
            g_pd[q * NTOK + row0]     = best0;  g_pi[q * NTOK + row0]     = bi0;
            g_pd[q * NTOK + row0 + 8] = best1;  g_pi[q * NTOK + row0 + 8] = bi1;
        }
    }
}

// ---------------- combine: reduce 4 quarters, gather, NCHW scatter ---------
__global__ void vq_combine(const float* __restrict__ cb, float* __restrict__ out) {
    const int t = blockIdx.x * blockDim.x + threadIdx.x;
    float best = g_pd[t];
    int   bi   = g_pi[t];
    #pragma unroll
    for (int qq = 1; qq < 4; ++qq) {          // ascending q => strict < keeps lowest idx
        float d = g_pd[qq * NTOK + t];
        int   i = g_pi[qq * NTOK + t];
        if (d < best) { best = d; bi = i; }
    }
    const int b = t >> 12, hw = t & (HW - 1);
    const float4* e  = (const float4*)cb + bi * (D / 4);
    float*        op = out + (size_t)b * D * HW + hw;
    #pragma unroll
    for (int j = 0; j < D / 4; ++j) {
        float4 v = __ldg(e + j);
        op[(4 * j + 0) * HW] = v.x;
        op[(4 * j + 1) * HW] = v.y;
        op[(4 * j + 2) * HW] = v.z;
        op[(4 * j + 3) * HW] = v.w;
    }
}

extern "C" void kernel_launch(void* const* d_in, const int* in_sizes, int n_in,
                              void* d_out, int out_size) {
    const float* input    = (const float*)d_in[0];   // [16, 64, 64, 64] fp32 NCHW
    const float* codebook = (const float*)d_in[1];   // [1024, 64] fp32
    float*       out      = (float*)d_out;

    size_t smem_bytes = (size_t)(16384 + 16384 + 256) * sizeof(float);  // 132096
    cudaFuncSetAttribute(vq_main, cudaFuncAttributeMaxDynamicSharedMemorySize,
                         (int)smem_bytes);

    vq_prep<<<64, 1024>>>(codebook);
    vq_main<<<dim3(32, 4), 256, smem_bytes>>>(input);
    vq_combine<<<256, 256>>>(codebook, out);
}